// round 6
// baseline (speedup 1.0000x reference)
#include <cuda_runtime.h>
#include <cuda_fp16.h>
#include <cstdint>

#define FIN   64
#define FOUT  64
#define FH    128
#define LATD  512
#define NB    16
#define HW    16384
#define KTOT  53760
#define WS    106496   // fp16 elements of packed weights per sample

// per-sample fp16 element offsets of fragment-ordered weight buffers
#define WIN_HI   0        // O=128 I=64  (8192 ele), lo at +8192
#define WMIDA_HI 16384    // O=128 I=128 (16384),   lo at +16384
#define WMIDB_HI 49152
#define WOUT_HI  81920    // O=64 I=128  (8192),    lo at +8192
#define WSH_HI   98304    // O=64 I=64   (4096),    lo at +4096

__device__ __align__(16) __half g_wh[NB * WS];
__device__ __align__(16) float g_bias[NB * 512];

// ---------------- helpers ----------------
__device__ __forceinline__ uint32_t pack_f16x2(float f0, float f1) {
    uint32_t r;
    asm("cvt.rn.f16x2.f32 %0, %1, %2;" : "=r"(r) : "f"(f1), "f"(f0));
    return r;
}
__device__ __forceinline__ unsigned long long pack2(float a, float b) {
    unsigned long long r;
    asm("mov.b64 %0, {%1,%2};" : "=l"(r) : "r"(__float_as_uint(a)), "r"(__float_as_uint(b)));
    return r;
}
__device__ __forceinline__ void unpack2(unsigned long long v, float& a, float& b) {
    unsigned u0, u1;
    asm("mov.b64 {%0,%1}, %2;" : "=r"(u0), "=r"(u1) : "l"(v));
    a = __uint_as_float(u0); b = __uint_as_float(u1);
}
__device__ __forceinline__ void ffma2(unsigned long long& d, unsigned long long a, unsigned long long b) {
    asm("fma.rn.f32x2 %0, %1, %2, %0;" : "+l"(d) : "l"(a), "l"(b));
}

__device__ __forceinline__ void mma16816(float d[4],
    const uint32_t a[4], uint32_t b0, uint32_t b1)
{
    asm volatile(
        "mma.sync.aligned.m16n8k16.row.col.f32.f16.f16.f32 "
        "{%0,%1,%2,%3}, {%4,%5,%6,%7}, {%8,%9}, {%0,%1,%2,%3};"
        : "+f"(d[0]), "+f"(d[1]), "+f"(d[2]), "+f"(d[3])
        : "r"(a[0]), "r"(a[1]), "r"(a[2]), "r"(a[3]), "r"(b0), "r"(b1));
}

// ============================================================
// Kernel A: hypernetwork GEMM. Sample-major transposed lat pairs in
// smem (warp-broadcast LDS.128) + f32x2 FFMA. fp16 hi/lo fragment pack.
// ============================================================
__global__ __launch_bounds__(128) void hyper_kernel(
    const float* __restrict__ lat,
    const float* __restrict__ Wm,
    const float* __restrict__ bias)
{
    __shared__ __align__(16) unsigned long long slat2[LATD][8];   // 32 KB
    for (int idx = threadIdx.x; idx < LATD * 8; idx += 128) {
        int l = idx >> 3, j = idx & 7;
        slat2[l][j] = pack2(lat[(2 * j) * LATD + l], lat[(2 * j + 1) * LATD + l]);
    }
    __syncthreads();

    int k = blockIdx.x * 128 + threadIdx.x;   // 420*128 == 53760 exact

    unsigned long long acc2[8];
#pragma unroll
    for (int j = 0; j < 8; j++) acc2[j] = 0ull;

    const float4* wr = (const float4*)(Wm + (size_t)k * LATD);
#pragma unroll 2
    for (int l4 = 0; l4 < LATD / 4; l4++) {
        float4 w = wr[l4];
        float wv[4] = {w.x, w.y, w.z, w.w};
#pragma unroll
        for (int i = 0; i < 4; i++) {
            int l = l4 * 4 + i;
            unsigned long long ad = pack2(wv[i], wv[i]);
            const ulonglong2* p = (const ulonglong2*)slat2[l];
            ulonglong2 q0 = p[0], q1 = p[1], q2 = p[2], q3 = p[3];
            ffma2(acc2[0], ad, q0.x); ffma2(acc2[1], ad, q0.y);
            ffma2(acc2[2], ad, q1.x); ffma2(acc2[3], ad, q1.y);
            ffma2(acc2[4], ad, q2.x); ffma2(acc2[5], ad, q2.y);
            ffma2(acc2[6], ad, q3.x); ffma2(acc2[7], ad, q3.y);
        }
    }

    const float RS128 = 0.08838834764831845f;  // 1/sqrt(128)
    const float RS64  = 0.125f;                // 1/sqrt(64)
    float bk = bias[k];

    // map k -> (layer, o, i) -> fragment element index
    bool isBias = false;
    float scale = 1.f;
    int o = 0, i = 0, I = 0, baseHi = 0, loDelta = 0;
    if (k < 8192) {
        o = k >> 6; i = k & 63; I = 64;
        baseHi = WIN_HI; loDelta = 8192; scale = RS128;
    } else if (k < 24576) {
        int idx = k - 8192; o = idx >> 7; i = idx & 127; I = 128;
        baseHi = WMIDA_HI; loDelta = 16384; scale = RS128;
    } else if (k < 40960) {
        int idx = k - 24576; o = idx >> 7; i = idx & 127; I = 128;
        baseHi = WMIDB_HI; loDelta = 16384; scale = RS128;
    } else if (k < 49152) {
        int idx = k - 40960; o = idx >> 7; i = idx & 127; I = 128;
        baseHi = WOUT_HI; loDelta = 8192; scale = RS64;
    } else if (k < 53248) {
        int idx = k - 49152; o = idx >> 6; i = idx & 63; I = 64;
        baseHi = WSH_HI; loDelta = 4096; scale = RS64;
    } else {
        isBias = true;
    }

    int fel = 0;
    if (!isBias) {
        int KT = I / 16;
        int nt = o >> 3, kt = i >> 4;
        int tl = (o & 7) * 4 + ((i & 7) >> 1);          // lane
        int el = (((i >> 3) & 1) << 1) | (i & 1);       // elem within 4-group
        fel = baseHi + ((nt * KT + kt) * 32 + tl) * 4 + el;
    }

#pragma unroll
    for (int j = 0; j < 8; j++) {
        float v0, v1;
        unpack2(acc2[j], v0, v1);
        float vs[2] = {v0, v1};
#pragma unroll
        for (int s2 = 0; s2 < 2; s2++) {
            int s = 2 * j + s2;
            if (isBias) {
                g_bias[s * 512 + (k - 53248)] = vs[s2] + bk;
            } else {
                float v = (vs[s2] + bk) * scale;
                __half h = __float2half_rn(v);
                __half l = __float2half_rn(v - __half2float(h));
                g_wh[(size_t)s * WS + fel]           = h;
                g_wh[(size_t)s * WS + fel + loDelta] = l;
            }
        }
    }
}

// ============================================================
// Kernel B: mma.sync fused block, M=32 per warp (two m16 halves share
// every B fragment -> B smem traffic halved). D transient per 2-nt chunk
// with bias folded into init; activations register-resident fp16.
// ============================================================

// one fused layer producing 128 channels: N[c][..] fragments (c = 0..7)
template <int KT>
__device__ __forceinline__ void layer_fused(
    const uint32_t (*A0)[4], const uint32_t (*A1)[4],
    uint32_t (*N0)[4], uint32_t (*N1)[4],
    const char* __restrict__ sm, int hiOff, int loOff,
    const float* __restrict__ bsm, int lane, int tig)
{
#pragma unroll
    for (int c = 0; c < 8; c++) {        // chunk = 2 nt = 16 channels
        float D[2][2][4];
#pragma unroll
        for (int j = 0; j < 2; j++) {
            int nt = c * 2 + j;
            float b0 = bsm[nt * 8 + tig * 2];
            float b1 = bsm[nt * 8 + tig * 2 + 1];
#pragma unroll
            for (int m = 0; m < 2; m++) {
                D[m][j][0] = b0; D[m][j][1] = b1;
                D[m][j][2] = b0; D[m][j][3] = b1;
            }
        }
#pragma unroll
        for (int kt = 0; kt < KT; kt++) {
            uint2 bh[2], bl[2];
#pragma unroll
            for (int j = 0; j < 2; j++) {
                int fo = (((c * 2 + j) * KT + kt) * 32 + lane) * 8;
                bh[j] = *(const uint2*)(sm + hiOff + fo);
                bl[j] = *(const uint2*)(sm + loOff + fo);
            }
#pragma unroll
            for (int j = 0; j < 2; j++) {
                mma16816(D[0][j], A0[kt], bh[j].x, bh[j].y);
                mma16816(D[1][j], A1[kt], bh[j].x, bh[j].y);
            }
#pragma unroll
            for (int j = 0; j < 2; j++) {
                mma16816(D[0][j], A0[kt], bl[j].x, bl[j].y);
                mma16816(D[1][j], A1[kt], bl[j].x, bl[j].y);
            }
        }
        // relu + fp16 pack -> next-layer A fragments (kt' = c)
#pragma unroll
        for (int m = 0; m < 2; m++) {
            uint32_t (*N)[4] = m ? N1 : N0;
            N[c][0] = pack_f16x2(fmaxf(D[m][0][0], 0.f), fmaxf(D[m][0][1], 0.f));
            N[c][1] = pack_f16x2(fmaxf(D[m][0][2], 0.f), fmaxf(D[m][0][3], 0.f));
            N[c][2] = pack_f16x2(fmaxf(D[m][1][0], 0.f), fmaxf(D[m][1][1], 0.f));
            N[c][3] = pack_f16x2(fmaxf(D[m][1][2], 0.f), fmaxf(D[m][1][3], 0.f));
        }
    }
}

__global__ __launch_bounds__(256, 1) void conv_kernel(
    const float* __restrict__ x, float* __restrict__ out)
{
    extern __shared__ __align__(16) char smem[];
    const float* bsm = (const float*)(smem + 212992);

    const int tid = threadIdx.x;
    const int w = tid >> 5, lane = tid & 31;
    const int gid = lane >> 2, tig = lane & 3;
    const int b  = blockIdx.x / 9;
    const int cs = blockIdx.x % 9;

    // stage all fragment-ordered weights (212992 B) + biases (2 KB)
    {
        const uint4* src = (const uint4*)(g_wh + (size_t)b * WS);
        uint4* dst = (uint4*)smem;
        for (int i = tid; i < 13312; i += 256) dst[i] = src[i];
        const float4* bsrc = (const float4*)(g_bias + b * 512);
        float4* bdst = (float4*)(smem + 212992);
        if (tid < 128) bdst[tid] = bsrc[tid];
    }
    __syncthreads();

    const float* xb = x + (size_t)b * FIN * HW;
    float* ob = out + (size_t)b * FOUT * HW;

    uint32_t X[2][4][4];
    uint32_t Abuf[2][2][8][4];   // ping-pong [pp][half][kt][4]

    for (int t = cs; t < 64; t += 9) {
        const int base = t * 256 + w * 32;

        // ---- load x as fp16 A fragments for both m16 halves ----
#pragma unroll
        for (int m = 0; m < 2; m++) {
            const int px_lo = base + m * 16 + gid;
            const int px_hi = px_lo + 8;
#pragma unroll
            for (int kt = 0; kt < 4; kt++) {
                const float* xp = xb + (size_t)(kt * 16 + tig * 2) * HW;
                X[m][kt][0] = pack_f16x2(xp[px_lo],          xp[HW + px_lo]);
                X[m][kt][1] = pack_f16x2(xp[px_hi],          xp[HW + px_hi]);
                X[m][kt][2] = pack_f16x2(xp[8 * HW + px_lo], xp[9 * HW + px_lo]);
                X[m][kt][3] = pack_f16x2(xp[8 * HW + px_hi], xp[9 * HW + px_hi]);
            }
        }

        // ---- layer in (KT=4): x -> Abuf[0] ----
        layer_fused<4>(X[0], X[1], Abuf[0][0], Abuf[0][1],
                       smem, WIN_HI * 2, (WIN_HI + 8192) * 2, bsm + 0, lane, tig);
        // ---- layer mida (KT=8): Abuf[0] -> Abuf[1] ----
        layer_fused<8>(Abuf[0][0], Abuf[0][1], Abuf[1][0], Abuf[1][1],
                       smem, WMIDA_HI * 2, (WMIDA_HI + 16384) * 2, bsm + 128, lane, tig);
        // ---- layer midb (KT=8): Abuf[1] -> Abuf[0] ----
        layer_fused<8>(Abuf[1][0], Abuf[1][1], Abuf[0][0], Abuf[0][1],
                       smem, WMIDB_HI * 2, (WMIDB_HI + 16384) * 2, bsm + 256, lane, tig);

        // ---- out layer: Wout @ h + Wshort @ x, 64 ch, store ----
#pragma unroll
        for (int c = 0; c < 4; c++) {
            float D[2][2][4];
#pragma unroll
            for (int j = 0; j < 2; j++) {
                int nt = c * 2 + j;
                int ch = nt * 8 + tig * 2;
                float b0 = bsm[384 + ch]     + bsm[448 + ch];
                float b1 = bsm[384 + ch + 1] + bsm[448 + ch + 1];
#pragma unroll
                for (int m = 0; m < 2; m++) {
                    D[m][j][0] = b0; D[m][j][1] = b1;
                    D[m][j][2] = b0; D[m][j][3] = b1;
                }
            }
#pragma unroll
            for (int kt = 0; kt < 8; kt++) {
                uint2 bh[2], bl[2];
#pragma unroll
                for (int j = 0; j < 2; j++) {
                    int fo = (((c * 2 + j) * 8 + kt) * 32 + lane) * 8;
                    bh[j] = *(const uint2*)(smem + WOUT_HI * 2 + fo);
                    bl[j] = *(const uint2*)(smem + (WOUT_HI + 8192) * 2 + fo);
                }
#pragma unroll
                for (int j = 0; j < 2; j++) {
                    mma16816(D[0][j], Abuf[0][0][kt], bh[j].x, bh[j].y);
                    mma16816(D[1][j], Abuf[0][1][kt], bh[j].x, bh[j].y);
                }
#pragma unroll
                for (int j = 0; j < 2; j++) {
                    mma16816(D[0][j], Abuf[0][0][kt], bl[j].x, bl[j].y);
                    mma16816(D[1][j], Abuf[0][1][kt], bl[j].x, bl[j].y);
                }
            }
#pragma unroll
            for (int kt = 0; kt < 4; kt++) {
                uint2 bh[2], bl[2];
#pragma unroll
                for (int j = 0; j < 2; j++) {
                    int fo = (((c * 2 + j) * 4 + kt) * 32 + lane) * 8;
                    bh[j] = *(const uint2*)(smem + WSH_HI * 2 + fo);
                    bl[j] = *(const uint2*)(smem + (WSH_HI + 4096) * 2 + fo);
                }
#pragma unroll
                for (int j = 0; j < 2; j++) {
                    mma16816(D[0][j], X[0][kt], bh[j].x, bh[j].y);
                    mma16816(D[1][j], X[1][kt], bh[j].x, bh[j].y);
                }
#pragma unroll
                for (int j = 0; j < 2; j++) {
                    mma16816(D[0][j], X[0][kt], bl[j].x, bl[j].y);
                    mma16816(D[1][j], X[1][kt], bl[j].x, bl[j].y);
                }
            }
            // store 16 channels x 32 pixels
#pragma unroll
            for (int m = 0; m < 2; m++) {
                const int px_lo = base + m * 16 + gid;
                const int px_hi = px_lo + 8;
#pragma unroll
                for (int j = 0; j < 2; j++) {
                    int ch = (c * 2 + j) * 8 + tig * 2;
                    float* op = ob + (size_t)ch * HW;
                    op[px_lo]      = D[m][j][0];
                    op[HW + px_lo] = D[m][j][1];
                    op[px_hi]      = D[m][j][2];
                    op[HW + px_hi] = D[m][j][3];
                }
            }
        }
    }
}

// ============================================================
extern "C" void kernel_launch(void* const* d_in, const int* in_sizes, int n_in,
                              void* d_out, int out_size)
{
    (void)in_sizes; (void)n_in; (void)out_size;
    const float* x    = (const float*)d_in[0];
    const float* lat  = (const float*)d_in[1];
    const float* W    = (const float*)d_in[2];
    const float* bias = (const float*)d_in[3];
    float* out = (float*)d_out;

    hyper_kernel<<<KTOT / 128, 128>>>(lat, W, bias);

    cudaFuncSetAttribute(conv_kernel,
                         cudaFuncAttributeMaxDynamicSharedMemorySize, 215040);
    conv_kernel<<<16 * 9, 256, 215040>>>(x, out);
}